// round 15
// baseline (speedup 1.0000x reference)
#include <cuda_runtime.h>
#include <cuda_fp16.h>
#include <math.h>

// Problem constants
#define B_    16
#define T_    64
#define H_    1024
#define D_    2048      // 2H
#define EMB_  512
#define MO_   1024      // maxout units
#define V_    32000
#define G3_   3072      // 3H
#define CAT_  3584      // H + EMB + D
#define NBLK  148       // persistent grid
#define NA_   96        // blocks doing W_hh mma (4 tiles each, uniform)

// recur smem layout (bytes)
#define WT4_BYTES  (4 * 128 * 72 * 4)    // 147456 (4 tiles, tf32, pitch 72)
#define HSPITCH    1026
#define HS_A_OFF   WT4_BYTES             // mma blocks: 14 Hih cols
#define WORK_OFF   204912                // sa/part/e workspace (21312 B)
#define DSMEM2     226224

// fp16 GEMM smem (3-stage pipeline, words)
#define HA_P   20
#define HB_P   136
#define H128_AS (3 * 128 * HA_P)
#define H128_SMEM ((H128_AS + 3 * 16 * HB_P) * 4)    // 56832
#define H256_AS (3 * 256 * HA_P)
#define H256_SMEM ((H256_AS + 3 * 16 * HB_P) * 4)    // 87552

// ---------------- scratch (device globals) ----------------------------------
__device__ float g_hemb[B_ * T_ * T_];
__device__ float g_Hih [B_ * T_ * G3_];
__device__ float g_s   [B_ * H_];
__device__ float g_E   [T_ * B_ * T_];
__device__ float g_gpart[9 * B_ * G3_];
__device__ float g_alignpart[2][B_][T_];
__device__ float g_cat [T_ * B_ * CAT_];
__device__ unsigned g_barcnt;
__device__ volatile unsigned g_barsense;
// packed half2 operands
__device__ unsigned g_h_p  [B_ * T_ * (D_ / 2)];
__device__ unsigned g_Wh_p [(D_ / 2) * T_];
__device__ unsigned g_Wih_p[(D_ / 2) * G3_];
__device__ unsigned g_Wemb_p[(H_ / 2) * EMB_];
__device__ unsigned g_Wt_p [(CAT_ / 2) * 2 * MO_];   // column-interleaved (m, m+MO)
__device__ unsigned g_Wout_p[(MO_ / 2) * V_];
__device__ unsigned g_cath [T_ * B_ * (CAT_ / 2)];
__device__ unsigned g_tmaxh[T_ * B_ * (MO_ / 2)];

// ---------------------------------------------------------------------------
__global__ void init_kernel() {
    int i = blockIdx.x * blockDim.x + threadIdx.x;
    if (i < B_ * H_) g_s[i] = 0.0f;
    if (i < 2 * B_ * T_) ((float*)g_alignpart)[i] = 0.0f;
    if (i == 0) { g_barcnt = 0; g_barsense = 0; }
}

// ---------------- helpers ----------------------------------------------------
__device__ __forceinline__ unsigned f2tf(float f) {
    unsigned r; asm("cvt.rna.tf32.f32 %0, %1;" : "=r"(r) : "f"(f)); return r;
}
__device__ __forceinline__ unsigned f2h2(float a, float b) {
    __half2 h = __floats2half2_rn(a, b);
    return *reinterpret_cast<unsigned*>(&h);
}
__device__ __forceinline__ void cpa16(unsigned smem, const void* g) {
    asm volatile("cp.async.cg.shared.global [%0], [%1], 16;" :: "r"(smem), "l"(g));
}
#define CP_COMMIT() asm volatile("cp.async.commit_group;" ::: "memory")
#define CP_WAIT(n)  asm volatile("cp.async.wait_group %0;" :: "n"(n) : "memory")
#define HMMA16(d, a, b)                                                     \
    asm volatile(                                                           \
        "mma.sync.aligned.m16n8k16.row.col.f32.f16.f16.f32 "                \
        "{%0,%1,%2,%3}, {%4,%5,%6,%7}, {%8,%9}, {%0,%1,%2,%3};"             \
        : "+f"(d[0]), "+f"(d[1]), "+f"(d[2]), "+f"(d[3])                    \
        : "r"(a[0]), "r"(a[1]), "r"(a[2]), "r"(a[3]), "r"(b[0]), "r"(b[1]))

// ---------------- pack kernels ----------------------------------------------
__global__ void pack_rows_kernel(const float* __restrict__ src,
                                 unsigned* __restrict__ dst,
                                 int rows, int nw, int src_ld, int dst_ld)
{
    int i = blockIdx.x * blockDim.x + threadIdx.x;
    if (i < rows * nw) {
        int r = i / nw, w = i - r * nw;
        float2 v = *reinterpret_cast<const float2*>(&src[(size_t)r * src_ld + 2 * w]);
        dst[(size_t)r * dst_ld + w] = f2h2(v.x, v.y);
    }
}
__global__ void pack_b_kernel(const float* __restrict__ src,
                              unsigned* __restrict__ dst, int K2, int N)
{
    int i = blockIdx.x * blockDim.x + threadIdx.x;
    if (i < K2 * N) {
        int k2 = i / N, n = i - k2 * N;
        dst[i] = f2h2(src[(size_t)(2 * k2) * N + n],
                      src[(size_t)(2 * k2 + 1) * N + n]);
    }
}
// W_t pack, maxout-interleaved columns: packed col j -> orig (j&1 ? j/2+MO : j/2)
__global__ void pack_bt_kernel(const float* __restrict__ src,
                               unsigned* __restrict__ dst, int K2, int N)
{
    int i = blockIdx.x * blockDim.x + threadIdx.x;
    if (i < K2 * N) {
        int k2 = i / N, j = i - k2 * N;
        int orig = (j & 1) ? (j >> 1) + MO_ : (j >> 1);
        dst[i] = f2h2(src[(size_t)(2 * k2) * N + orig],
                      src[(size_t)(2 * k2 + 1) * N + orig]);
    }
}

// ---------------- fp16 GEMM, 128x128x32, 3-stage cp.async -------------------
// MAXOUT: interleaved-pair epilogue -> fmax -> packed half2 into Cv (word rows)
template <bool MAXOUT>
__global__ __launch_bounds__(256, 2)
void hmma_gemm_kernel(const unsigned* __restrict__ Ap, int ldaW,
                      const unsigned* __restrict__ Bp, int ldbW,
                      void* __restrict__ Cv, int ldc,
                      const float* __restrict__ bias, int K, int ncols)
{
    extern __shared__ unsigned char gsm[];
    unsigned* AS = (unsigned*)gsm;
    unsigned* BS = AS + H128_AS;

    const int tid = threadIdx.x;
    const int wid = tid >> 5, lane = tid & 31;
    const int wm = wid & 3, wn = wid >> 2;
    const int m0 = blockIdx.y * 128, n0 = blockIdx.x * 128;

    const int arow = tid >> 1, aw = (tid & 1) * 8;
    const int kp = tid >> 4, bc = (tid & 15) * 8;
    int colb = n0 + bc;
    if (colb > ncols - 8) colb = ncols - 8;

    float acc[2][8][4];
#pragma unroll
    for (int mi = 0; mi < 2; mi++)
#pragma unroll
        for (int ni = 0; ni < 8; ni++)
#pragma unroll
            for (int u = 0; u < 4; u++) acc[mi][ni][u] = 0.0f;

    auto stageA = [&](int p, int k0) {
        const unsigned* as = Ap + (size_t)(m0 + arow) * ldaW + (k0 >> 1) + aw;
        unsigned sm = (unsigned)__cvta_generic_to_shared(
            AS + p * (128 * HA_P) + arow * HA_P + aw);
        cpa16(sm, as); cpa16(sm + 16, as + 4);
        const unsigned* bs = Bp + (size_t)((k0 >> 1) + kp) * ldbW + colb;
        unsigned smb = (unsigned)__cvta_generic_to_shared(
            BS + p * (16 * HB_P) + kp * HB_P + bc);
        cpa16(smb, bs); cpa16(smb + 16, bs + 4);
    };
    auto compute = [&](int p) {
        const unsigned* A0 = AS + p * (128 * HA_P);
        const unsigned* B0 = BS + p * (16 * HB_P);
#pragma unroll
        for (int ks = 0; ks < 2; ks++) {
            unsigned af[2][4], bf[8][2];
#pragma unroll
            for (int mi = 0; mi < 2; mi++) {
                int r = wm * 32 + mi * 16 + (lane >> 2);
                af[mi][0] = A0[r * HA_P + ks * 8 + (lane & 3)];
                af[mi][1] = A0[(r + 8) * HA_P + ks * 8 + (lane & 3)];
                af[mi][2] = A0[r * HA_P + ks * 8 + (lane & 3) + 4];
                af[mi][3] = A0[(r + 8) * HA_P + ks * 8 + (lane & 3) + 4];
            }
#pragma unroll
            for (int ni = 0; ni < 8; ni++) {
                int c = wn * 64 + ni * 8 + (lane >> 2);
                bf[ni][0] = B0[(ks * 8 + (lane & 3)) * HB_P + c];
                bf[ni][1] = B0[(ks * 8 + (lane & 3) + 4) * HB_P + c];
            }
#pragma unroll
            for (int mi = 0; mi < 2; mi++)
#pragma unroll
                for (int ni = 0; ni < 8; ni++)
                    HMMA16(acc[mi][ni], af[mi], bf[ni]);
        }
    };

    stageA(0, 0);  CP_COMMIT();
    stageA(1, 32); CP_COMMIT();
    int buf = 0;
    for (int k0 = 64; k0 < K; k0 += 32) {
        CP_WAIT(1);
        __syncthreads();
        compute(buf);
        int nb = buf + 2; if (nb >= 3) nb -= 3;
        stageA(nb, k0); CP_COMMIT();
        buf = (buf == 2) ? 0 : buf + 1;
    }
    CP_WAIT(1); __syncthreads(); compute(buf);
    buf = (buf == 2) ? 0 : buf + 1;
    CP_WAIT(0); __syncthreads(); compute(buf);

#pragma unroll
    for (int mi = 0; mi < 2; mi++) {
        int r = m0 + wm * 32 + mi * 16 + (lane >> 2);
        int r8 = r + 8;
#pragma unroll
        for (int ni = 0; ni < 8; ni++) {
            int c = n0 + wn * 64 + ni * 8 + (lane & 3) * 2;
            if (MAXOUT) {
                // interleaved pair (c, c+1) = (orig m, orig m+MO); maxout idx m=c/2
                const int m = c >> 1;
                float bt0 = bias[m], bt1 = bias[m + MO_];
                float mx0 = fmaxf(acc[mi][ni][0] + bt0, acc[mi][ni][1] + bt1);
                float mx1 = fmaxf(acc[mi][ni][2] + bt0, acc[mi][ni][3] + bt1);
                float o0 = __shfl_down_sync(0xffffffffu, mx0, 1);
                float o1 = __shfl_down_sync(0xffffffffu, mx1, 1);
                if ((lane & 1) == 0) {
                    unsigned* Cw = (unsigned*)Cv;
                    const int w = m >> 1;
                    Cw[(size_t)r * ldc + w]  = f2h2(mx0, o0);
                    Cw[(size_t)r8 * ldc + w] = f2h2(mx1, o1);
                }
            } else if (c < ncols) {
                float* C = (float*)Cv;
                float bc0 = bias[c], bc1 = bias[c + 1];
                C[(size_t)r * ldc + c]      = acc[mi][ni][0] + bc0;
                C[(size_t)r * ldc + c + 1]  = acc[mi][ni][1] + bc1;
                C[(size_t)r8 * ldc + c]     = acc[mi][ni][2] + bc0;
                C[(size_t)r8 * ldc + c + 1] = acc[mi][ni][3] + bc1;
            }
        }
    }
}

// ---------------- fp16 GEMM, 256x128x32, 3-stage cp.async (vocab) -----------
__global__ __launch_bounds__(256, 1)
void hmma_gemm256_kernel(const unsigned* __restrict__ Ap, int ldaW,
                         const unsigned* __restrict__ Bp, int ldbW,
                         float* __restrict__ C, int ldc,
                         const float* __restrict__ bias, int K, int ncols)
{
    extern __shared__ unsigned char gsm[];
    unsigned* AS = (unsigned*)gsm;
    unsigned* BS = AS + H256_AS;

    const int tid = threadIdx.x;
    const int wid = tid >> 5, lane = tid & 31;
    const int wm = wid & 3, wn = wid >> 2;
    const int m0 = blockIdx.y * 256, n0 = blockIdx.x * 128;

    const int arow = tid >> 1, aw = (tid & 1) * 8;
    const int kp = tid >> 4, bc = (tid & 15) * 8;
    int colb = n0 + bc;
    if (colb > ncols - 8) colb = ncols - 8;

    float acc[4][8][4];
#pragma unroll
    for (int mi = 0; mi < 4; mi++)
#pragma unroll
        for (int ni = 0; ni < 8; ni++)
#pragma unroll
            for (int u = 0; u < 4; u++) acc[mi][ni][u] = 0.0f;

    auto stageA = [&](int p, int k0) {
#pragma unroll
        for (int h = 0; h < 2; h++) {
            const int r = arow + h * 128;
            const unsigned* as = Ap + (size_t)(m0 + r) * ldaW + (k0 >> 1) + aw;
            unsigned sm = (unsigned)__cvta_generic_to_shared(
                AS + p * (256 * HA_P) + r * HA_P + aw);
            cpa16(sm, as); cpa16(sm + 16, as + 4);
        }
        const unsigned* bs = Bp + (size_t)((k0 >> 1) + kp) * ldbW + colb;
        unsigned smb = (unsigned)__cvta_generic_to_shared(
            BS + p * (16 * HB_P) + kp * HB_P + bc);
        cpa16(smb, bs); cpa16(smb + 16, bs + 4);
    };
    auto compute = [&](int p) {
        const unsigned* A0 = AS + p * (256 * HA_P);
        const unsigned* B0 = BS + p * (16 * HB_P);
#pragma unroll
        for (int ks = 0; ks < 2; ks++) {
            unsigned af[4][4], bf[8][2];
#pragma unroll
            for (int mi = 0; mi < 4; mi++) {
                int r = wm * 64 + mi * 16 + (lane >> 2);
                af[mi][0] = A0[r * HA_P + ks * 8 + (lane & 3)];
                af[mi][1] = A0[(r + 8) * HA_P + ks * 8 + (lane & 3)];
                af[mi][2] = A0[r * HA_P + ks * 8 + (lane & 3) + 4];
                af[mi][3] = A0[(r + 8) * HA_P + ks * 8 + (lane & 3) + 4];
            }
#pragma unroll
            for (int ni = 0; ni < 8; ni++) {
                int c = wn * 64 + ni * 8 + (lane >> 2);
                bf[ni][0] = B0[(ks * 8 + (lane & 3)) * HB_P + c];
                bf[ni][1] = B0[(ks * 8 + (lane & 3) + 4) * HB_P + c];
            }
#pragma unroll
            for (int mi = 0; mi < 4; mi++)
#pragma unroll
                for (int ni = 0; ni < 8; ni++)
                    HMMA16(acc[mi][ni], af[mi], bf[ni]);
        }
    };

    stageA(0, 0);  CP_COMMIT();
    stageA(1, 32); CP_COMMIT();
    int buf = 0;
    for (int k0 = 64; k0 < K; k0 += 32) {
        CP_WAIT(1);
        __syncthreads();
        compute(buf);
        int nb = buf + 2; if (nb >= 3) nb -= 3;
        stageA(nb, k0); CP_COMMIT();
        buf = (buf == 2) ? 0 : buf + 1;
    }
    CP_WAIT(1); __syncthreads(); compute(buf);
    buf = (buf == 2) ? 0 : buf + 1;
    CP_WAIT(0); __syncthreads(); compute(buf);

#pragma unroll
    for (int mi = 0; mi < 4; mi++) {
        int r = m0 + wm * 64 + mi * 16 + (lane >> 2);
        int r0 = (r & (B_ - 1)) * T_ + (r >> 4);        // PERMUTE (vocab)
        int r8 = r + 8;
        int r1 = (r8 & (B_ - 1)) * T_ + (r8 >> 4);
#pragma unroll
        for (int ni = 0; ni < 8; ni++) {
            int c = n0 + wn * 64 + ni * 8 + (lane & 3) * 2;
            if (c < ncols) {
                float bc0 = bias[c], bc1 = bias[c + 1];
                C[(size_t)r0 * ldc + c]     = acc[mi][ni][0] + bc0;
                C[(size_t)r0 * ldc + c + 1] = acc[mi][ni][1] + bc1;
                C[(size_t)r1 * ldc + c]     = acc[mi][ni][2] + bc0;
                C[(size_t)r1 * ldc + c + 1] = acc[mi][ni][3] + bc1;
            }
        }
    }
}

// ---------------- grid-wide sense barrier (atomic; measured best, R13) ------
__device__ __forceinline__ void gsync(unsigned target) {
    __syncthreads();
    if (threadIdx.x == 0) {
        __threadfence();
        unsigned old = atomicAdd(&g_barcnt, 1);
        if (old == NBLK - 1) {
            g_barcnt = 0;
            __threadfence();
            g_barsense = target;
        } else {
            while (g_barsense < target) { __nanosleep(32); }
        }
        __threadfence();
    }
    __syncthreads();
}

// ---------------- persistent recurrence kernel ------------------------------
// Uniform phase A: blocks 0..95 each own EXACTLY 4 W_hh tiles (q=bid&7,
// chunks gidx*4..+4) -> 2 identical mma rounds every step, no imbalance.
// Those blocks hold 14 Hih cols; blocks 96..147 hold 33-34 Hih cols (smem
// re-laid per role). Phase B (blocks 0..31) and barriers = R13 verbatim.
__global__ __launch_bounds__(512, 1)
void recur_kernel(const float* __restrict__ Whh,
                  const float* __restrict__ Ws,
                  const float* __restrict__ bs,
                  const float* __restrict__ bhh)
{
    extern __shared__ unsigned char dsm[];
    const int tid = threadIdx.x;
    const int bid = blockIdx.x;
    const int lane = tid & 31, wid = tid >> 5;
    const bool isA = (bid < NA_);

    unsigned* wt_all = (unsigned*)dsm;
    float*    hs     = (float*)(dsm + (isA ? HS_A_OFF : 0));
    unsigned (*sa)[136]     = (unsigned(*)[136])(dsm + WORK_OFF);
    float    (*part)[16][66] = (float(*)[16][66])(dsm + WORK_OFF + 8704);
    float    (*e_sh)[65]    = (float(*)[65])(dsm + WORK_OFF + 17152);
    float*    s2            = (float*)(dsm + WORK_OFF);
    float    (*redp)[64]    = (float(*)[64])(dsm + WORK_OFF + 2048);

    const int q = bid & 7;
    const int c0t = (bid >> 3) * 4;            // 4 tiles (only if isA)
    const int ntile = isA ? 4 : 0;

    // Hih column ownership
    int c0h, ncolsh;
    if (isA) { c0h = bid * 14; ncolsh = 14; }
    else {
        c0h = 1344 + ((bid - NA_) * 1728) / 52;
        ncolsh = (1344 + ((bid - NA_ + 1) * 1728) / 52) - c0h;   // 33 or 34
    }

    // preload W_hh tiles (tf32)
    for (int j = 0; j < ntile; j++) {
        const int c = c0t + j;
        const int rr = tid >> 4, c4 = (tid & 15) * 4;
        unsigned* wt = wt_all + j * (128 * 72);
#pragma unroll
        for (int p = 0; p < 4; p++) {
            int row = p * 32 + rr;
            float4 v = *reinterpret_cast<const float4*>(
                &Whh[(size_t)(q * 128 + row) * G3_ + c * 64 + c4]);
            wt[row * 72 + c4 + 0] = f2tf(v.x);
            wt[row * 72 + c4 + 1] = f2tf(v.y);
            wt[row * 72 + c4 + 2] = f2tf(v.z);
            wt[row * 72 + c4 + 3] = f2tf(v.w);
        }
    }
    // preload Hih cols (fp32, transposed)
    for (int p = tid; p < 1024 * ncolsh; p += 512) {
        int row = p / ncolsh, cl = p - row * ncolsh;
        hs[cl * HSPITCH + row] = g_Hih[(size_t)row * G3_ + c0h + cl];
    }
    __syncthreads();

    const int half = wid >> 3;
    const int hwid = wid & 7;
    const int wk = hwid >> 2, wn = hwid & 3;

    unsigned bar = 0;
    for (int i = 0; i < T_; i++) {
        // ---- phase A: stage s (q slice) once (mma blocks only) ----
        if (isA) {
            const int b = tid >> 5, c4 = (tid & 31) * 4;
            float4 v = *reinterpret_cast<const float4*>(&g_s[b * H_ + q * 128 + c4]);
            sa[b][c4 + 0] = f2tf(v.x); sa[b][c4 + 1] = f2tf(v.y);
            sa[b][c4 + 2] = f2tf(v.z); sa[b][c4 + 3] = f2tf(v.w);
            __syncthreads();
        }
        // ---- phase A: s@W_hh, 2 uniform rounds of 2 tiles ----
        for (int jj = 0; jj < ntile; jj += 2) {
            const int j = jj + half;
            float acc[2][4];
#pragma unroll
            for (int ni = 0; ni < 2; ni++)
#pragma unroll
                for (int u = 0; u < 4; u++) acc[ni][u] = 0.0f;
            {
                const unsigned* wt = wt_all + j * (128 * 72);
#pragma unroll
                for (int k8 = 0; k8 < 8; k8++) {
                    const int kb = wk * 64 + k8 * 8;
                    unsigned af[4];
                    af[0] = sa[lane >> 2][kb + (lane & 3)];
                    af[1] = sa[(lane >> 2) + 8][kb + (lane & 3)];
                    af[2] = sa[lane >> 2][kb + (lane & 3) + 4];
                    af[3] = sa[(lane >> 2) + 8][kb + (lane & 3) + 4];
#pragma unroll
                    for (int ni = 0; ni < 2; ni++) {
                        const int cc = wn * 16 + ni * 8 + (lane >> 2);
                        unsigned bf0 = wt[(kb + (lane & 3)) * 72 + cc];
                        unsigned bf1 = wt[(kb + (lane & 3) + 4) * 72 + cc];
                        asm volatile(
                            "mma.sync.aligned.m16n8k8.row.col.f32.tf32.tf32.f32 "
                            "{%0,%1,%2,%3}, {%4,%5,%6,%7}, {%8,%9}, {%0,%1,%2,%3};"
                            : "+f"(acc[ni][0]), "+f"(acc[ni][1]),
                              "+f"(acc[ni][2]), "+f"(acc[ni][3])
                            : "r"(af[0]), "r"(af[1]), "r"(af[2]), "r"(af[3]),
                              "r"(bf0), "r"(bf1));
                    }
                }
            }
            __syncthreads();
            if (wk == 1) {
#pragma unroll
                for (int ni = 0; ni < 2; ni++) {
                    const int r = lane >> 2, cc = wn * 16 + ni * 8 + (lane & 3) * 2;
                    part[half][r][cc]         = acc[ni][0];
                    part[half][r][cc + 1]     = acc[ni][1];
                    part[half][r + 8][cc]     = acc[ni][2];
                    part[half][r + 8][cc + 1] = acc[ni][3];
                }
            }
            __syncthreads();
            if (wk == 0) {
                const int c = c0t + j;
#pragma unroll
                for (int ni = 0; ni < 2; ni++) {
                    const int r = lane >> 2, cc = wn * 16 + ni * 8 + (lane & 3) * 2;
                    const int gc = c * 64 + cc;
                    g_gpart[(size_t)(q * 16 + r) * G3_ + gc] =
                        acc[ni][0] + part[half][r][cc];
                    g_gpart[(size_t)(q * 16 + r) * G3_ + gc + 1] =
                        acc[ni][1] + part[half][r][cc + 1];
                    g_gpart[(size_t)(q * 16 + r + 8) * G3_ + gc] =
                        acc[ni][2] + part[half][r + 8][cc];
                    g_gpart[(size_t)(q * 16 + r + 8) * G3_ + gc + 1] =
                        acc[ni][3] + part[half][r + 8][cc + 1];
                }
            }
            __syncthreads();
        }
        // ---- phase A: softmax (first 256 threads; identical arithmetic) ----
        if (tid < 256) {
            const int b2 = (tid >> 5) * 2 + (lane >> 4);
            const int j0 = (lane & 15) * 4;
            float a[4];
#pragma unroll
            for (int u = 0; u < 4; u++) {
                int jx = j0 + u;
                float v = bs[jx] + g_hemb[(b2 * T_ + i) * T_ + jx];
#pragma unroll
                for (int kc = 0; kc < 2; kc++) v += g_alignpart[kc][b2][jx];
                a[u] = tanhf(v);
            }
            float m = fmaxf(fmaxf(a[0], a[1]), fmaxf(a[2], a[3]));
#pragma unroll
            for (int o = 8; o > 0; o >>= 1)
                m = fmaxf(m, __shfl_xor_sync(0xffffffffu, m, o));
            float ex[4], ssum = 0.0f;
#pragma unroll
            for (int u = 0; u < 4; u++) { ex[u] = __expf(a[u] - m); ssum += ex[u]; }
#pragma unroll
            for (int o = 8; o > 0; o >>= 1)
                ssum += __shfl_xor_sync(0xffffffffu, ssum, o);
            float inv = 1.0f / ssum;
#pragma unroll
            for (int u = 0; u < 4; u++) {
                e_sh[b2][j0 + u] = ex[u] * inv;
                if (bid == 0) g_E[(i * B_ + b2) * T_ + j0 + u] = ex[u] * inv;
            }
        }
        __syncthreads();
        // ---- phase A: gi = e @ Hih (smem Hih) ----
        for (int p = tid; p < 16 * ncolsh; p += 512) {
            const int b = p / ncolsh, cl = p - b * ncolsh;
            const float* hrow = hs + cl * HSPITCH + b * 64;
            float a0 = 0.0f, a1 = 0.0f;
#pragma unroll
            for (int t = 0; t < 64; t += 4) {
                float2 h0 = *reinterpret_cast<const float2*>(hrow + t);
                float2 h1 = *reinterpret_cast<const float2*>(hrow + t + 2);
                a0 += e_sh[b][t] * h0.x + e_sh[b][t + 1] * h0.y;
                a1 += e_sh[b][t + 2] * h1.x + e_sh[b][t + 3] * h1.y;
            }
            g_gpart[(size_t)(8 * 16 + b) * G3_ + c0h + cl] = a0 + a1;
        }
        gsync(++bar);
        // ---- phase B: GRU pointwise + s@W_s (blocks 0..31) ----
        if (bid < 32) {
            const int b = bid >> 1, hf = bid & 1;
            const int k = hf * 512 + tid;

            float gr = bhh[k], gz = bhh[H_ + k], hn = bhh[2 * H_ + k];
#pragma unroll
            for (int qq = 0; qq < 8; qq++) {
                const float* P = g_gpart + (size_t)(qq * 16 + b) * G3_;
                gr += P[k]; gz += P[H_ + k]; hn += P[2 * H_ + k];
            }
            const float* P8 = g_gpart + (size_t)(8 * 16 + b) * G3_;
            gr += P8[k]; gz += P8[H_ + k];
            float inn = P8[2 * H_ + k];

            float r = 1.0f / (1.0f + __expf(-gr));
            float z = 1.0f / (1.0f + __expf(-gz));
            float n = tanhf(inn + r * hn);
            float sold = g_s[b * H_ + k];
            float snew = (1.0f - z) * n + z * sold;
            g_s[b * H_ + k] = snew;
            g_cat[(size_t)(i * B_ + b) * CAT_ + k] = snew;

            s2[tid] = snew;
            __syncthreads();
            const int j = tid & 63, sub = tid >> 6;
            float a = 0.0f;
#pragma unroll 8
            for (int kk = 0; kk < 64; kk++)
                a += s2[sub * 64 + kk] *
                     Ws[(size_t)(hf * 512 + sub * 64 + kk) * T_ + j];
            redp[sub][j] = a;
            __syncthreads();
            if (tid < 64)
                g_alignpart[hf][b][tid] =
                    redp[0][tid] + redp[1][tid] + redp[2][tid] + redp[3][tid] +
                    redp[4][tid] + redp[5][tid] + redp[6][tid] + redp[7][tid];
        }
        gsync(++bar);
    }
}

// ---------------- batched context -------------------------------------------
__global__ __launch_bounds__(128)
void ctx_kernel(const float* __restrict__ h)
{
    const int b = blockIdx.x, dc = blockIdx.y, tid = threadIdx.x;
    __shared__ float sh_h[T_][128];
    __shared__ float e_sh[T_];
    const int dbase = dc * 128;
    for (int t = 0; t < T_; t++)
        sh_h[t][tid] = h[(size_t)(b * T_ + t) * D_ + dbase + tid];
    __syncthreads();
    for (int i = 0; i < T_; i++) {
        if (tid < 64) e_sh[tid] = g_E[(i * B_ + b) * T_ + tid];
        __syncthreads();
        float acc = 0.0f;
#pragma unroll 8
        for (int t = 0; t < T_; t++) acc += e_sh[t] * sh_h[t][tid];
        g_cat[(size_t)(i * B_ + b) * CAT_ + H_ + EMB_ + dbase + tid] = acc;
        __syncthreads();
    }
}

// ---------------------------------------------------------------------------
extern "C" void kernel_launch(void* const* d_in, const int* in_sizes, int n_in,
                              void* d_out, int out_size)
{
    (void)in_sizes; (void)n_in; (void)out_size;
    const float* h     = (const float*)d_in[0];
    const float* W_h   = (const float*)d_in[1];
    const float* b_h   = (const float*)d_in[2];
    const float* W_s   = (const float*)d_in[3];
    const float* b_s   = (const float*)d_in[4];
    const float* W_ih  = (const float*)d_in[5];
    const float* b_ih  = (const float*)d_in[6];
    const float* W_hh  = (const float*)d_in[7];
    const float* b_hh  = (const float*)d_in[8];
    const float* W_emb = (const float*)d_in[9];
    const float* b_emb = (const float*)d_in[10];
    const float* W_t   = (const float*)d_in[11];
    const float* b_t   = (const float*)d_in[12];
    const float* W_out = (const float*)d_in[13];
    const float* b_out = (const float*)d_in[14];
    float* out = (float*)d_out;

    float *p_hemb, *p_Hih, *p_cat;
    unsigned *p_hp, *p_Whp, *p_Wihp, *p_Wembp, *p_Wtp, *p_Woutp, *p_cath, *p_tmaxh;
    cudaGetSymbolAddress((void**)&p_hemb, g_hemb);
    cudaGetSymbolAddress((void**)&p_Hih,  g_Hih);
    cudaGetSymbolAddress((void**)&p_cat,  g_cat);
    cudaGetSymbolAddress((void**)&p_hp,   g_h_p);
    cudaGetSymbolAddress((void**)&p_Whp,  g_Wh_p);
    cudaGetSymbolAddress((void**)&p_Wihp, g_Wih_p);
    cudaGetSymbolAddress((void**)&p_Wembp, g_Wemb_p);
    cudaGetSymbolAddress((void**)&p_Wtp,  g_Wt_p);
    cudaGetSymbolAddress((void**)&p_Woutp, g_Wout_p);
    cudaGetSymbolAddress((void**)&p_cath, g_cath);
    cudaGetSymbolAddress((void**)&p_tmaxh, g_tmaxh);

    static int smem_set = 0;
    if (!smem_set) {
        cudaFuncSetAttribute(recur_kernel,
            cudaFuncAttributeMaxDynamicSharedMemorySize, DSMEM2);
        cudaFuncSetAttribute(hmma_gemm_kernel<false>,
            cudaFuncAttributeMaxDynamicSharedMemorySize, H128_SMEM);
        cudaFuncSetAttribute(hmma_gemm_kernel<true>,
            cudaFuncAttributeMaxDynamicSharedMemorySize, H128_SMEM);
        cudaFuncSetAttribute(hmma_gemm256_kernel,
            cudaFuncAttributeMaxDynamicSharedMemorySize, H256_SMEM);
        smem_set = 1;
    }

    init_kernel<<<(B_ * H_ + 255) / 256, 256>>>();

    // ---- packs (weights + h) ----
    pack_rows_kernel<<<(B_ * T_ * (D_ / 2) + 255) / 256, 256>>>(
        h, p_hp, B_ * T_, D_ / 2, D_, D_ / 2);
    pack_b_kernel<<<((D_ / 2) * T_ + 255) / 256, 256>>>(W_h, p_Whp, D_ / 2, T_);
    pack_b_kernel<<<((D_ / 2) * G3_ + 255) / 256, 256>>>(W_ih, p_Wihp, D_ / 2, G3_);
    pack_b_kernel<<<((H_ / 2) * EMB_ + 255) / 256, 256>>>(W_emb, p_Wembp, H_ / 2, EMB_);
    pack_bt_kernel<<<((CAT_ / 2) * 2 * MO_ + 255) / 256, 256>>>(W_t, p_Wtp, CAT_ / 2, 2 * MO_);
    pack_b_kernel<<<((MO_ / 2) * V_ + 255) / 256, 256>>>(W_out, p_Woutp, MO_ / 2, V_);

    // ---- precompute: hemb, Hih ----
    hmma_gemm_kernel<false><<<dim3(1, (B_ * T_) / 128), 256, H128_SMEM>>>(
        p_hp, D_ / 2, p_Whp, T_, p_hemb, T_, b_h, D_, T_);
    hmma_gemm_kernel<false><<<dim3(G3_ / 128, (B_ * T_) / 128), 256, H128_SMEM>>>(
        p_hp, D_ / 2, p_Wihp, G3_, p_Hih, G3_, b_ih, D_, G3_);

    // ---- persistent recurrence ----
    recur_kernel<<<NBLK, 512, DSMEM2>>>(W_hh, W_s, b_s, b_hh);

    // ---- epilogue ----
    ctx_kernel<<<dim3(B_, D_ / 128), 128>>>(h);
    pack_rows_kernel<<<(T_ * B_ * (H_ / 2) + 255) / 256, 256>>>(
        p_cat, p_cath, T_ * B_, H_ / 2, CAT_, CAT_ / 2);
    hmma_gemm_kernel<false><<<dim3(EMB_ / 128, (T_ * B_) / 128), 256, H128_SMEM>>>(
        p_cath, CAT_ / 2, p_Wembp, EMB_, p_cat + H_, CAT_, b_emb, H_, EMB_);
    pack_rows_kernel<<<(T_ * B_ * ((EMB_ + D_) / 2) + 255) / 256, 256>>>(
        p_cat + H_, p_cath + H_ / 2, T_ * B_, (EMB_ + D_) / 2, CAT_, CAT_ / 2);
    // t_tilde GEMM with fused maxout -> packed half2 (interleaved W_t)
    hmma_gemm_kernel<true><<<dim3(2 * MO_ / 128, (T_ * B_) / 128), 256, H128_SMEM>>>(
        p_cath, CAT_ / 2, p_Wtp, 2 * MO_, p_tmaxh, MO_ / 2, b_t, CAT_, 2 * MO_);
    hmma_gemm256_kernel<<<dim3(V_ / 128, (T_ * B_) / 256), 256, H256_SMEM>>>(
        p_tmaxh, MO_ / 2, p_Woutp, V_, out, V_, b_out, MO_, V_);
}

// round 16
// speedup vs baseline: 1.0677x; 1.0677x over previous
#include <cuda_runtime.h>
#include <cuda_fp16.h>
#include <math.h>

// Problem constants
#define B_    16
#define T_    64
#define H_    1024
#define D_    2048      // 2H
#define EMB_  512
#define MO_   1024      // maxout units
#define V_    32000
#define G3_   3072      // 3H
#define CAT_  3584      // H + EMB + D
#define NBLK  148       // persistent grid

// Dynamic smem layout for recur_kernel (bytes)  [fp16 W_hh tiles]
#define WT_ELEMS   (64 * 72)             // one W_hh tile, half2 words, pitch 72
#define WHH_BYTES  (3 * WT_ELEMS * 4)    // 55296
#define HSPITCH    1026
#define HS_OFF     WHH_BYTES
#define HS_BYTES   (21 * HSPITCH * 4 + 24)   // 86208
#define SA_OFF     (WHH_BYTES + HS_BYTES)    // 141504 (s tile half2 / pB scratch)
#define PART_OFF   (SA_OFF + 4352)           // 145856
#define E_OFF      (PART_OFF + 8448)         // 154304
#define DSMEM_BYTES (E_OFF + 4160)           // 158464

// fp16 GEMM smem (3-stage pipeline, words)
#define HA_P   20
#define HB_P   136
#define H128_AS (3 * 128 * HA_P)
#define H128_SMEM ((H128_AS + 3 * 16 * HB_P) * 4)    // 56832
#define H256_AS (3 * 256 * HA_P)
#define H256_SMEM ((H256_AS + 3 * 16 * HB_P) * 4)    // 87552

// ---------------- scratch (device globals) ----------------------------------
__device__ float g_hemb[B_ * T_ * T_];
__device__ float g_Hih [B_ * T_ * G3_];
__device__ float g_s   [B_ * H_];
__device__ float g_E   [T_ * B_ * T_];
__device__ float g_gpart[9 * B_ * G3_];
__device__ float g_alignpart[2][B_][T_];
__device__ float g_cat [T_ * B_ * CAT_];
__device__ float g_tt  [T_ * B_ * 2 * MO_];
__device__ unsigned g_barcnt;
__device__ volatile unsigned g_barsense;
// packed half2 operands
__device__ unsigned g_h_p  [B_ * T_ * (D_ / 2)];
__device__ unsigned g_Wh_p [(D_ / 2) * T_];
__device__ unsigned g_Wih_p[(D_ / 2) * G3_];
__device__ unsigned g_Wemb_p[(H_ / 2) * EMB_];
__device__ unsigned g_Wt_p [(CAT_ / 2) * 2 * MO_];
__device__ unsigned g_Wout_p[(MO_ / 2) * V_];
__device__ unsigned g_cath [T_ * B_ * (CAT_ / 2)];
__device__ unsigned g_tmaxh[T_ * B_ * (MO_ / 2)];

// ---------------------------------------------------------------------------
__global__ void init_kernel() {
    int i = blockIdx.x * blockDim.x + threadIdx.x;
    if (i < B_ * H_) g_s[i] = 0.0f;
    if (i < 2 * B_ * T_) ((float*)g_alignpart)[i] = 0.0f;
    if (i == 0) { g_barcnt = 0; g_barsense = 0; }
}

// ---------------- helpers ----------------------------------------------------
__device__ __forceinline__ unsigned f2h2(float a, float b) {
    __half2 h = __floats2half2_rn(a, b);
    return *reinterpret_cast<unsigned*>(&h);
}
__device__ __forceinline__ void cpa16(unsigned smem, const void* g) {
    asm volatile("cp.async.cg.shared.global [%0], [%1], 16;" :: "r"(smem), "l"(g));
}
#define CP_COMMIT() asm volatile("cp.async.commit_group;" ::: "memory")
#define CP_WAIT(n)  asm volatile("cp.async.wait_group %0;" :: "n"(n) : "memory")
#define HMMA16(d, a, b)                                                     \
    asm volatile(                                                           \
        "mma.sync.aligned.m16n8k16.row.col.f32.f16.f16.f32 "                \
        "{%0,%1,%2,%3}, {%4,%5,%6,%7}, {%8,%9}, {%0,%1,%2,%3};"             \
        : "+f"(d[0]), "+f"(d[1]), "+f"(d[2]), "+f"(d[3])                    \
        : "r"(a[0]), "r"(a[1]), "r"(a[2]), "r"(a[3]), "r"(b[0]), "r"(b[1]))

// ---------------- pack kernels ----------------------------------------------
__global__ void pack_rows_kernel(const float* __restrict__ src,
                                 unsigned* __restrict__ dst,
                                 int rows, int nw, int src_ld, int dst_ld)
{
    int i = blockIdx.x * blockDim.x + threadIdx.x;
    if (i < rows * nw) {
        int r = i / nw, w = i - r * nw;
        float2 v = *reinterpret_cast<const float2*>(&src[(size_t)r * src_ld + 2 * w]);
        dst[(size_t)r * dst_ld + w] = f2h2(v.x, v.y);
    }
}
__global__ void pack_b_kernel(const float* __restrict__ src,
                              unsigned* __restrict__ dst, int K2, int N)
{
    int i = blockIdx.x * blockDim.x + threadIdx.x;
    if (i < K2 * N) {
        int k2 = i / N, n = i - k2 * N;
        dst[i] = f2h2(src[(size_t)(2 * k2) * N + n],
                      src[(size_t)(2 * k2 + 1) * N + n]);
    }
}

// ---------------- fp16 GEMM, 128x128x32, 3-stage cp.async -------------------
template <bool PERMUTE>
__global__ __launch_bounds__(256, 2)
void hmma_gemm_kernel(const unsigned* __restrict__ Ap, int ldaW,
                      const unsigned* __restrict__ Bp, int ldbW,
                      float* __restrict__ C, int ldc,
                      const float* __restrict__ bias, int K, int ncols)
{
    extern __shared__ unsigned char gsm[];
    unsigned* AS = (unsigned*)gsm;
    unsigned* BS = AS + H128_AS;

    const int tid = threadIdx.x;
    const int wid = tid >> 5, lane = tid & 31;
    const int wm = wid & 3, wn = wid >> 2;
    const int m0 = blockIdx.y * 128, n0 = blockIdx.x * 128;

    const int arow = tid >> 1, aw = (tid & 1) * 8;
    const int kp = tid >> 4, bc = (tid & 15) * 8;
    int colb = n0 + bc;
    if (colb > ncols - 8) colb = ncols - 8;

    float acc[2][8][4];
#pragma unroll
    for (int mi = 0; mi < 2; mi++)
#pragma unroll
        for (int ni = 0; ni < 8; ni++)
#pragma unroll
            for (int u = 0; u < 4; u++) acc[mi][ni][u] = 0.0f;

    auto stageA = [&](int p, int k0) {
        const unsigned* as = Ap + (size_t)(m0 + arow) * ldaW + (k0 >> 1) + aw;
        unsigned sm = (unsigned)__cvta_generic_to_shared(
            AS + p * (128 * HA_P) + arow * HA_P + aw);
        cpa16(sm, as); cpa16(sm + 16, as + 4);
        const unsigned* bs = Bp + (size_t)((k0 >> 1) + kp) * ldbW + colb;
        unsigned smb = (unsigned)__cvta_generic_to_shared(
            BS + p * (16 * HB_P) + kp * HB_P + bc);
        cpa16(smb, bs); cpa16(smb + 16, bs + 4);
    };
    auto compute = [&](int p) {
        const unsigned* A0 = AS + p * (128 * HA_P);
        const unsigned* B0 = BS + p * (16 * HB_P);
#pragma unroll
        for (int ks = 0; ks < 2; ks++) {
            unsigned af[2][4], bf[8][2];
#pragma unroll
            for (int mi = 0; mi < 2; mi++) {
                int r = wm * 32 + mi * 16 + (lane >> 2);
                af[mi][0] = A0[r * HA_P + ks * 8 + (lane & 3)];
                af[mi][1] = A0[(r + 8) * HA_P + ks * 8 + (lane & 3)];
                af[mi][2] = A0[r * HA_P + ks * 8 + (lane & 3) + 4];
                af[mi][3] = A0[(r + 8) * HA_P + ks * 8 + (lane & 3) + 4];
            }
#pragma unroll
            for (int ni = 0; ni < 8; ni++) {
                int c = wn * 64 + ni * 8 + (lane >> 2);
                bf[ni][0] = B0[(ks * 8 + (lane & 3)) * HB_P + c];
                bf[ni][1] = B0[(ks * 8 + (lane & 3) + 4) * HB_P + c];
            }
#pragma unroll
            for (int mi = 0; mi < 2; mi++)
#pragma unroll
                for (int ni = 0; ni < 8; ni++)
                    HMMA16(acc[mi][ni], af[mi], bf[ni]);
        }
    };

    stageA(0, 0);  CP_COMMIT();
    stageA(1, 32); CP_COMMIT();
    int buf = 0;
    for (int k0 = 64; k0 < K; k0 += 32) {
        CP_WAIT(1);
        __syncthreads();
        compute(buf);
        int nb = buf + 2; if (nb >= 3) nb -= 3;
        stageA(nb, k0); CP_COMMIT();
        buf = (buf == 2) ? 0 : buf + 1;
    }
    CP_WAIT(1); __syncthreads(); compute(buf);
    buf = (buf == 2) ? 0 : buf + 1;
    CP_WAIT(0); __syncthreads(); compute(buf);

#pragma unroll
    for (int mi = 0; mi < 2; mi++) {
        int r = m0 + wm * 32 + mi * 16 + (lane >> 2);
        int r0 = PERMUTE ? ((r & (B_ - 1)) * T_ + (r >> 4)) : r;
        int r8 = r + 8;
        int r1 = PERMUTE ? ((r8 & (B_ - 1)) * T_ + (r8 >> 4)) : r8;
#pragma unroll
        for (int ni = 0; ni < 8; ni++) {
            int c = n0 + wn * 64 + ni * 8 + (lane & 3) * 2;
            if (c < ncols) {
                float bc0 = bias[c], bc1 = bias[c + 1];
                C[(size_t)r0 * ldc + c]     = acc[mi][ni][0] + bc0;
                C[(size_t)r0 * ldc + c + 1] = acc[mi][ni][1] + bc1;
                C[(size_t)r1 * ldc + c]     = acc[mi][ni][2] + bc0;
                C[(size_t)r1 * ldc + c + 1] = acc[mi][ni][3] + bc1;
            }
        }
    }
}

// ---------------- fp16 GEMM, 256x128x32, 3-stage cp.async (vocab) -----------
__global__ __launch_bounds__(256, 1)
void hmma_gemm256_kernel(const unsigned* __restrict__ Ap, int ldaW,
                         const unsigned* __restrict__ Bp, int ldbW,
                         float* __restrict__ C, int ldc,
                         const float* __restrict__ bias, int K, int ncols)
{
    extern __shared__ unsigned char gsm[];
    unsigned* AS = (unsigned*)gsm;
    unsigned* BS = AS + H256_AS;

    const int tid = threadIdx.x;
    const int wid = tid >> 5, lane = tid & 31;
    const int wm = wid & 3, wn = wid >> 2;
    const int m0 = blockIdx.y * 256, n0 = blockIdx.x * 128;

    const int arow = tid >> 1, aw = (tid & 1) * 8;
    const int kp = tid >> 4, bc = (tid & 15) * 8;
    int colb = n0 + bc;
    if (colb > ncols - 8) colb = ncols - 8;

    float acc[4][8][4];
#pragma unroll
    for (int mi = 0; mi < 4; mi++)
#pragma unroll
        for (int ni = 0; ni < 8; ni++)
#pragma unroll
            for (int u = 0; u < 4; u++) acc[mi][ni][u] = 0.0f;

    auto stageA = [&](int p, int k0) {
#pragma unroll
        for (int h = 0; h < 2; h++) {
            const int r = arow + h * 128;
            const unsigned* as = Ap + (size_t)(m0 + r) * ldaW + (k0 >> 1) + aw;
            unsigned sm = (unsigned)__cvta_generic_to_shared(
                AS + p * (256 * HA_P) + r * HA_P + aw);
            cpa16(sm, as); cpa16(sm + 16, as + 4);
        }
        const unsigned* bs = Bp + (size_t)((k0 >> 1) + kp) * ldbW + colb;
        unsigned smb = (unsigned)__cvta_generic_to_shared(
            BS + p * (16 * HB_P) + kp * HB_P + bc);
        cpa16(smb, bs); cpa16(smb + 16, bs + 4);
    };
    auto compute = [&](int p) {
        const unsigned* A0 = AS + p * (256 * HA_P);
        const unsigned* B0 = BS + p * (16 * HB_P);
#pragma unroll
        for (int ks = 0; ks < 2; ks++) {
            unsigned af[4][4], bf[8][2];
#pragma unroll
            for (int mi = 0; mi < 4; mi++) {
                int r = wm * 64 + mi * 16 + (lane >> 2);
                af[mi][0] = A0[r * HA_P + ks * 8 + (lane & 3)];
                af[mi][1] = A0[(r + 8) * HA_P + ks * 8 + (lane & 3)];
                af[mi][2] = A0[r * HA_P + ks * 8 + (lane & 3) + 4];
                af[mi][3] = A0[(r + 8) * HA_P + ks * 8 + (lane & 3) + 4];
            }
#pragma unroll
            for (int ni = 0; ni < 8; ni++) {
                int c = wn * 64 + ni * 8 + (lane >> 2);
                bf[ni][0] = B0[(ks * 8 + (lane & 3)) * HB_P + c];
                bf[ni][1] = B0[(ks * 8 + (lane & 3) + 4) * HB_P + c];
            }
#pragma unroll
            for (int mi = 0; mi < 4; mi++)
#pragma unroll
                for (int ni = 0; ni < 8; ni++)
                    HMMA16(acc[mi][ni], af[mi], bf[ni]);
        }
    };

    stageA(0, 0);  CP_COMMIT();
    stageA(1, 32); CP_COMMIT();
    int buf = 0;
    for (int k0 = 64; k0 < K; k0 += 32) {
        CP_WAIT(1);
        __syncthreads();
        compute(buf);
        int nb = buf + 2; if (nb >= 3) nb -= 3;
        stageA(nb, k0); CP_COMMIT();
        buf = (buf == 2) ? 0 : buf + 1;
    }
    CP_WAIT(1); __syncthreads(); compute(buf);
    buf = (buf == 2) ? 0 : buf + 1;
    CP_WAIT(0); __syncthreads(); compute(buf);

#pragma unroll
    for (int mi = 0; mi < 4; mi++) {
        int r = m0 + wm * 64 + mi * 16 + (lane >> 2);
        int r0 = (r & (B_ - 1)) * T_ + (r >> 4);        // PERMUTE (vocab)
        int r8 = r + 8;
        int r1 = (r8 & (B_ - 1)) * T_ + (r8 >> 4);
#pragma unroll
        for (int ni = 0; ni < 8; ni++) {
            int c = n0 + wn * 64 + ni * 8 + (lane & 3) * 2;
            if (c < ncols) {
                float bc0 = bias[c], bc1 = bias[c + 1];
                C[(size_t)r0 * ldc + c]     = acc[mi][ni][0] + bc0;
                C[(size_t)r0 * ldc + c + 1] = acc[mi][ni][1] + bc1;
                C[(size_t)r1 * ldc + c]     = acc[mi][ni][2] + bc0;
                C[(size_t)r1 * ldc + c + 1] = acc[mi][ni][3] + bc1;
            }
        }
    }
}

// ---------------- grid-wide sense barrier (atomic; measured best) -----------
__device__ __forceinline__ void gsync(unsigned target) {
    __syncthreads();
    if (threadIdx.x == 0) {
        __threadfence();
        unsigned old = atomicAdd(&g_barcnt, 1);
        if (old == NBLK - 1) {
            g_barcnt = 0;
            __threadfence();
            g_barsense = target;
        } else {
            while (g_barsense < target) { __nanosleep(32); }
        }
        __threadfence();
    }
    __syncthreads();
}

// ---------------- persistent recurrence kernel (fp16 W_hh mma) --------------
// R13 structure; phase A s@W_hh mma converted tf32 m16n8k8 -> fp16 m16n8k16:
// half the mma instructions and smem fragment loads, W_hh smem halved.
__global__ __launch_bounds__(512, 1)
void recur_kernel(const float* __restrict__ Whh,
                  const float* __restrict__ Ws,
                  const float* __restrict__ bs,
                  const float* __restrict__ bhh)
{
    extern __shared__ unsigned char dsm[];
    unsigned* wt_all = (unsigned*)dsm;                     // [3][64 kp][72]
    float*    hs     = (float*)(dsm + HS_OFF);
    unsigned (*sa)[68]      = (unsigned(*)[68])(dsm + SA_OFF);   // s half2
    float    (*part)[16][66] = (float(*)[16][66])(dsm + PART_OFF);
    float    (*e_sh)[65]    = (float(*)[65])(dsm + E_OFF);
    float*    s2            = (float*)(dsm + SA_OFF);
    float    (*redp)[64]    = (float(*)[64])(dsm + SA_OFF + 2048);

    const int tid = threadIdx.x;
    const int bid = blockIdx.x;
    const int lane = tid & 31, wid = tid >> 5;

    const int q = bid & 7;
    const int gidx = bid >> 3;
    const int gcount = (q < 4) ? 19 : 18;
    const int c0t = gidx * 48 / gcount;
    const int c1t = (gidx + 1) * 48 / gcount;
    const int ntile = c1t - c0t;

    const int c0h = (G3_ * bid) / NBLK, c1h = (G3_ * (bid + 1)) / NBLK;
    const int ncolsh = c1h - c0h;

    // preload W_hh tiles, packed half2: word(kp,col) = (W[2kp][col], W[2kp+1][col])
    for (int j = 0; j < ntile; j++) {
        const int c = c0t + j;
        unsigned* wt = wt_all + j * WT_ELEMS;
        for (int idx = tid; idx < 64 * 64; idx += 512) {
            const int kp2 = idx >> 6, col = idx & 63;
            const float w0 = Whh[(size_t)(q * 128 + 2 * kp2) * G3_ + c * 64 + col];
            const float w1 = Whh[(size_t)(q * 128 + 2 * kp2 + 1) * G3_ + c * 64 + col];
            wt[kp2 * 72 + col] = f2h2(w0, w1);
        }
    }
    for (int p = tid; p < 1024 * ncolsh; p += 512) {
        int row = p / ncolsh, cl = p - row * ncolsh;
        hs[cl * HSPITCH + row] = g_Hih[(size_t)row * G3_ + c0h + cl];
    }
    __syncthreads();

    const int half = wid >> 3;
    const int hwid = wid & 7;
    const int wk = hwid >> 2, wn = hwid & 3;

    unsigned bar = 0;
    for (int i = 0; i < T_; i++) {
        // ---- phase A: stage s (q slice) once, packed half2 ----
        {
            const int row = tid >> 5, w2 = tid & 31;
            float4 v = *reinterpret_cast<const float4*>(
                &g_s[row * H_ + q * 128 + w2 * 4]);
            sa[row][w2 * 2]     = f2h2(v.x, v.y);
            sa[row][w2 * 2 + 1] = f2h2(v.z, v.w);
        }
        __syncthreads();
        // ---- phase A: s@W_hh, two tiles at a time (fp16 mma) ----
        for (int jj = 0; jj < ntile; jj += 2) {
            const int nt = (ntile - jj < 2) ? (ntile - jj) : 2;
            const int j = jj + half;
            float acc[2][4];
#pragma unroll
            for (int ni = 0; ni < 2; ni++)
#pragma unroll
                for (int u = 0; u < 4; u++) acc[ni][u] = 0.0f;
            if (half < nt) {
                const unsigned* wt = wt_all + j * WT_ELEMS;
#pragma unroll
                for (int it = 0; it < 4; it++) {
                    const int kb = wk * 32 + it * 8;   // kp base (16 k per iter)
                    unsigned af[4];
                    af[0] = sa[lane >> 2][kb + (lane & 3)];
                    af[1] = sa[(lane >> 2) + 8][kb + (lane & 3)];
                    af[2] = sa[lane >> 2][kb + (lane & 3) + 4];
                    af[3] = sa[(lane >> 2) + 8][kb + (lane & 3) + 4];
#pragma unroll
                    for (int ni = 0; ni < 2; ni++) {
                        const int cc = wn * 16 + ni * 8 + (lane >> 2);
                        unsigned bfv[2];
                        bfv[0] = wt[(kb + (lane & 3)) * 72 + cc];
                        bfv[1] = wt[(kb + (lane & 3) + 4) * 72 + cc];
                        HMMA16(acc[ni], af, bfv);
                    }
                }
            }
            __syncthreads();
            if (half < nt && wk == 1) {
#pragma unroll
                for (int ni = 0; ni < 2; ni++) {
                    const int r = lane >> 2, cc = wn * 16 + ni * 8 + (lane & 3) * 2;
                    part[half][r][cc]         = acc[ni][0];
                    part[half][r][cc + 1]     = acc[ni][1];
                    part[half][r + 8][cc]     = acc[ni][2];
                    part[half][r + 8][cc + 1] = acc[ni][3];
                }
            }
            __syncthreads();
            if (half < nt && wk == 0) {
                const int c = c0t + j;
#pragma unroll
                for (int ni = 0; ni < 2; ni++) {
                    const int r = lane >> 2, cc = wn * 16 + ni * 8 + (lane & 3) * 2;
                    const int gc = c * 64 + cc;
                    g_gpart[(size_t)(q * 16 + r) * G3_ + gc] =
                        acc[ni][0] + part[half][r][cc];
                    g_gpart[(size_t)(q * 16 + r) * G3_ + gc + 1] =
                        acc[ni][1] + part[half][r][cc + 1];
                    g_gpart[(size_t)(q * 16 + r + 8) * G3_ + gc] =
                        acc[ni][2] + part[half][r + 8][cc];
                    g_gpart[(size_t)(q * 16 + r + 8) * G3_ + gc + 1] =
                        acc[ni][3] + part[half][r + 8][cc + 1];
                }
            }
            __syncthreads();
        }
        // ---- phase A: softmax (first 256 threads; identical arithmetic) ----
        if (tid < 256) {
            const int b2 = (tid >> 5) * 2 + (lane >> 4);
            const int j0 = (lane & 15) * 4;
            float a[4];
#pragma unroll
            for (int u = 0; u < 4; u++) {
                int jx = j0 + u;
                float v = bs[jx] + g_hemb[(b2 * T_ + i) * T_ + jx];
#pragma unroll
                for (int kc = 0; kc < 2; kc++) v += g_alignpart[kc][b2][jx];
                a[u] = tanhf(v);
            }
            float m = fmaxf(fmaxf(a[0], a[1]), fmaxf(a[2], a[3]));
#pragma unroll
            for (int o = 8; o > 0; o >>= 1)
                m = fmaxf(m, __shfl_xor_sync(0xffffffffu, m, o));
            float ex[4], ssum = 0.0f;
#pragma unroll
            for (int u = 0; u < 4; u++) { ex[u] = __expf(a[u] - m); ssum += ex[u]; }
#pragma unroll
            for (int o = 8; o > 0; o >>= 1)
                ssum += __shfl_xor_sync(0xffffffffu, ssum, o);
            float inv = 1.0f / ssum;
#pragma unroll
            for (int u = 0; u < 4; u++) {
                e_sh[b2][j0 + u] = ex[u] * inv;
                if (bid == 0) g_E[(i * B_ + b2) * T_ + j0 + u] = ex[u] * inv;
            }
        }
        __syncthreads();
        // ---- phase A: gi = e @ Hih (smem Hih) ----
        for (int p = tid; p < 16 * ncolsh; p += 512) {
            const int b = p / ncolsh, cl = p - b * ncolsh;
            const float* hrow = hs + cl * HSPITCH + b * 64;
            float a0 = 0.0f, a1 = 0.0f;
#pragma unroll
            for (int t = 0; t < 64; t += 4) {
                float2 h0 = *reinterpret_cast<const float2*>(hrow + t);
                float2 h1 = *reinterpret_cast<const float2*>(hrow + t + 2);
                a0 += e_sh[b][t] * h0.x + e_sh[b][t + 1] * h0.y;
                a1 += e_sh[b][t + 2] * h1.x + e_sh[b][t + 3] * h1.y;
            }
            g_gpart[(size_t)(8 * 16 + b) * G3_ + c0h + cl] = a0 + a1;
        }
        gsync(++bar);
        // ---- phase B: GRU pointwise + s@W_s (blocks 0..31) ----
        if (bid < 32) {
            const int b = bid >> 1, hf = bid & 1;
            const int k = hf * 512 + tid;

            float gr = bhh[k], gz = bhh[H_ + k], hn = bhh[2 * H_ + k];
#pragma unroll
            for (int qq = 0; qq < 8; qq++) {
                const float* P = g_gpart + (size_t)(qq * 16 + b) * G3_;
                gr += P[k]; gz += P[H_ + k]; hn += P[2 * H_ + k];
            }
            const float* P8 = g_gpart + (size_t)(8 * 16 + b) * G3_;
            gr += P8[k]; gz += P8[H_ + k];
            float inn = P8[2 * H_ + k];

            float r = 1.0f / (1.0f + __expf(-gr));
            float z = 1.0f / (1.0f + __expf(-gz));
            float n = tanhf(inn + r * hn);
            float sold = g_s[b * H_ + k];
            float snew = (1.0f - z) * n + z * sold;
            g_s[b * H_ + k] = snew;
            g_cat[(size_t)(i * B_ + b) * CAT_ + k] = snew;

            s2[tid] = snew;
            __syncthreads();
            const int j = tid & 63, sub = tid >> 6;
            float a = 0.0f;
#pragma unroll 8
            for (int kk = 0; kk < 64; kk++)
                a += s2[sub * 64 + kk] *
                     Ws[(size_t)(hf * 512 + sub * 64 + kk) * T_ + j];
            redp[sub][j] = a;
            __syncthreads();
            if (tid < 64)
                g_alignpart[hf][b][tid] =
                    redp[0][tid] + redp[1][tid] + redp[2][tid] + redp[3][tid] +
                    redp[4][tid] + redp[5][tid] + redp[6][tid] + redp[7][tid];
        }
        gsync(++bar);
    }
}

// ---------------- batched context -------------------------------------------
__global__ __launch_bounds__(128)
void ctx_kernel(const float* __restrict__ h)
{
    const int b = blockIdx.x, dc = blockIdx.y, tid = threadIdx.x;
    __shared__ float sh_h[T_][128];
    __shared__ float e_sh[T_];
    const int dbase = dc * 128;
    for (int t = 0; t < T_; t++)
        sh_h[t][tid] = h[(size_t)(b * T_ + t) * D_ + dbase + tid];
    __syncthreads();
    for (int i = 0; i < T_; i++) {
        if (tid < 64) e_sh[tid] = g_E[(i * B_ + b) * T_ + tid];
        __syncthreads();
        float acc = 0.0f;
#pragma unroll 8
        for (int t = 0; t < T_; t++) acc += e_sh[t] * sh_h[t][tid];
        g_cat[(size_t)(i * B_ + b) * CAT_ + H_ + EMB_ + dbase + tid] = acc;
        __syncthreads();
    }
}

// ---------------- maxout -> packed half2 ------------------------------------
__global__ void maxout_kernel()
{
    const int idx = blockIdx.x * blockDim.x + threadIdx.x;
    const int r = idx >> 9, m2 = idx & 511;
    const float* row = g_tt + (size_t)r * (2 * MO_);
    float a = fmaxf(row[2 * m2],     row[MO_ + 2 * m2]);
    float b = fmaxf(row[2 * m2 + 1], row[MO_ + 2 * m2 + 1]);
    g_tmaxh[idx] = f2h2(a, b);
}

// ---------------------------------------------------------------------------
extern "C" void kernel_launch(void* const* d_in, const int* in_sizes, int n_in,
                              void* d_out, int out_size)
{
    (void)in_sizes; (void)n_in; (void)out_size;
    const float* h     = (const float*)d_in[0];
    const float* W_h   = (const float*)d_in[1];
    const float* b_h   = (const float*)d_in[2];
    const float* W_s   = (const float*)d_in[3];
    const float* b_s   = (const float*)d_in[4];
    const float* W_ih  = (const float*)d_in[5];
    const float* b_ih  = (const float*)d_in[6];
    const float* W_hh  = (const float*)d_in[7];
    const float* b_hh  = (const float*)d_in[8];
    const float* W_emb = (const float*)d_in[9];
    const float* b_emb = (const float*)d_in[10];
    const float* W_t   = (const float*)d_in[11];
    const float* b_t   = (const float*)d_in[12];
    const float* W_out = (const float*)d_in[13];
    const float* b_out = (const float*)d_in[14];
    float* out = (float*)d_out;

    float *p_hemb, *p_Hih, *p_cat, *p_tt;
    unsigned *p_hp, *p_Whp, *p_Wihp, *p_Wembp, *p_Wtp, *p_Woutp, *p_cath, *p_tmaxh;
    cudaGetSymbolAddress((void**)&p_hemb, g_hemb);
    cudaGetSymbolAddress((void**)&p_Hih,  g_Hih);
    cudaGetSymbolAddress((void**)&p_cat,  g_cat);
    cudaGetSymbolAddress((void**)&p_tt,   g_tt);
    cudaGetSymbolAddress((void**)&p_hp,   g_h_p);
    cudaGetSymbolAddress((void**)&p_Whp,  g_Wh_p);
    cudaGetSymbolAddress((void**)&p_Wihp, g_Wih_p);
    cudaGetSymbolAddress((void**)&p_Wembp, g_Wemb_p);
    cudaGetSymbolAddress((void**)&p_Wtp,  g_Wt_p);
    cudaGetSymbolAddress((void**)&p_Woutp, g_Wout_p);
    cudaGetSymbolAddress((void**)&p_cath, g_cath);
    cudaGetSymbolAddress((void**)&p_tmaxh, g_tmaxh);

    static int smem_set = 0;
    if (!smem_set) {
        cudaFuncSetAttribute(recur_kernel,
            cudaFuncAttributeMaxDynamicSharedMemorySize, DSMEM_BYTES);
        cudaFuncSetAttribute(hmma_gemm_kernel<false>,
            cudaFuncAttributeMaxDynamicSharedMemorySize, H128_SMEM);
        cudaFuncSetAttribute(hmma_gemm256_kernel,
            cudaFuncAttributeMaxDynamicSharedMemorySize, H256_SMEM);
        smem_set = 1;
    }

    init_kernel<<<(B_ * H_ + 255) / 256, 256>>>();

    // ---- packs (weights + h) ----
    pack_rows_kernel<<<(B_ * T_ * (D_ / 2) + 255) / 256, 256>>>(
        h, p_hp, B_ * T_, D_ / 2, D_, D_ / 2);
    pack_b_kernel<<<((D_ / 2) * T_ + 255) / 256, 256>>>(W_h, p_Whp, D_ / 2, T_);
    pack_b_kernel<<<((D_ / 2) * G3_ + 255) / 256, 256>>>(W_ih, p_Wihp, D_ / 2, G3_);
    pack_b_kernel<<<((H_ / 2) * EMB_ + 255) / 256, 256>>>(W_emb, p_Wembp, H_ / 2, EMB_);
    pack_b_kernel<<<((CAT_ / 2) * 2 * MO_ + 255) / 256, 256>>>(W_t, p_Wtp, CAT_ / 2, 2 * MO_);
    pack_b_kernel<<<((MO_ / 2) * V_ + 255) / 256, 256>>>(W_out, p_Woutp, MO_ / 2, V_);

    // ---- precompute: hemb, Hih ----
    hmma_gemm_kernel<false><<<dim3(1, (B_ * T_) / 128), 256, H128_SMEM>>>(
        p_hp, D_ / 2, p_Whp, T_, p_hemb, T_, b_h, D_, T_);
    hmma_gemm_kernel<false><<<dim3(G3_ / 128, (B_ * T_) / 128), 256, H128_SMEM>>>(
        p_hp, D_ / 2, p_Wihp, G3_, p_Hih, G3_, b_ih, D_, G3_);

    // ---- persistent recurrence ----
    recur_kernel<<<NBLK, 512, DSMEM_BYTES>>>(W_hh, W_s, b_s, b_hh);

    // ---- epilogue ----
    ctx_kernel<<<dim3(B_, D_ / 128), 128>>>(h);
    pack_rows_kernel<<<(T_ * B_ * (H_ / 2) + 255) / 256, 256>>>(
        p_cat, p_cath, T_ * B_, H_ / 2, CAT_, CAT_ / 2);
    hmma_gemm_kernel<false><<<dim3(EMB_ / 128, (T_ * B_) / 128), 256, H128_SMEM>>>(
        p_cath, CAT_ / 2, p_Wembp, EMB_, p_cat + H_, CAT_, b_emb, H_, EMB_);
    pack_rows_kernel<<<(T_ * B_ * ((EMB_ + D_) / 2) + 255) / 256, 256>>>(
        p_cat + H_, p_cath + H_ / 2, T_ * B_, (EMB_ + D_) / 2, CAT_, CAT_ / 2);
    hmma_gemm_kernel<false><<<dim3(2 * MO_ / 128, (T_ * B_) / 128), 256, H128_SMEM>>>(
        p_cath, CAT_ / 2, p_Wtp, 2 * MO_, p_tt, 2 * MO_, b_t, CAT_, 2 * MO_);
    maxout_kernel<<<(T_ * B_ * (MO_ / 2)) / 256, 256>>>();
    hmma_gemm256_kernel<<<dim3(V_ / 128, (T_ * B_) / 256), 256, H256_SMEM>>>(
        p_tmaxh, MO_ / 2, p_Woutp, V_, out, V_, b_out, MO_, V_);
}